// round 3
// baseline (speedup 1.0000x reference)
#include <cuda_runtime.h>
#include <math.h>

#define N_NODES 50000
#define N_EDGES 800000

#define INV_SQRT8  0.35355339059327373f
#define INV_SQRT32 0.17677669529663687f
#define CG_INV3    0.5773502691896258f   // 1/sqrt(3)
#define CG_INV2    0.7071067811865476f   // 1/sqrt(2)
#define MS_SCALE   0.125f                // 1/sqrt(64)
#define MV_SCALE   0.10206207261596575f  // 1/sqrt(96)
#define NSC_SCALE  0.0625f               // 1/sqrt(256)
#define NEIGH_INV  0.25f                 // 1/sqrt(16)

// Scratch (static device memory — no allocation in kernel_launch)
__device__ __align__(16) float g_xs[N_NODES * 32];    // linear_1 scalar out
__device__ __align__(16) float g_xv[N_NODES * 96];    // linear_1 vector out, [N][3][32] comp-major
__device__ __align__(16) float g_aggs[N_NODES * 64];  // scatter target, [N][64]
__device__ __align__(16) float g_aggv[N_NODES * 288]; // scatter target, [N][3][96] comp-major

__device__ __forceinline__ void red_add_v4(float* addr, float a, float b, float c, float d) {
    asm volatile("red.global.add.v4.f32 [%0], {%1, %2, %3, %4};"
                 :: "l"(addr), "f"(a), "f"(b), "f"(c), "f"(d) : "memory");
}

// ---------------------------------------------------------------------------
// Kernel 0: zero the aggregation buffers
// ---------------------------------------------------------------------------
__global__ void zero_kernel() {
    const int stride = gridDim.x * blockDim.x;
    int i = blockIdx.x * blockDim.x + threadIdx.x;
    const float4 z = make_float4(0.f, 0.f, 0.f, 0.f);
    const int tot_s = N_NODES * 64 / 4;
    const int tot_v = N_NODES * 288 / 4;
    for (int k = i; k < tot_s; k += stride) reinterpret_cast<float4*>(g_aggs)[k] = z;
    for (int k = i; k < tot_v; k += stride) reinterpret_cast<float4*>(g_aggv)[k] = z;
}

// ---------------------------------------------------------------------------
// Kernel 1: linear_1 (per-l channel mixing), one warp per node
// ---------------------------------------------------------------------------
__global__ void lin1_kernel(const float* __restrict__ node_s,
                            const float* __restrict__ node_v,
                            const float* __restrict__ W1s,
                            const float* __restrict__ W1v) {
    __shared__ float sW1s[1024];
    __shared__ float sW1v[1024];
    for (int i = threadIdx.x; i < 1024; i += blockDim.x) {
        sW1s[i] = W1s[i];
        sW1v[i] = W1v[i];
    }
    __syncthreads();

    const int warp = (blockIdx.x * blockDim.x + threadIdx.x) >> 5;
    const int lane = threadIdx.x & 31;
    if (warp >= N_NODES) return;
    const int n = warp;

    float sl = node_s[n * 32 + lane];
    float acc = 0.f;
#pragma unroll
    for (int u = 0; u < 32; u++)
        acc += __shfl_sync(0xffffffffu, sl, u) * sW1s[u * 32 + lane];
    g_xs[n * 32 + lane] = acc * INV_SQRT32;

#pragma unroll
    for (int c = 0; c < 3; c++) {
        float vl = node_v[n * 96 + lane * 3 + c];
        float a = 0.f;
#pragma unroll
        for (int u = 0; u < 32; u++)
            a += __shfl_sync(0xffffffffu, vl, u) * sW1v[u * 32 + lane];
        g_xv[n * 96 + c * 32 + lane] = a * INV_SQRT32;
    }
}

// ---------------------------------------------------------------------------
// Kernel 2: per-edge radial MLP + CG tensor product + scatter via red.v4
// 8 threads per edge; thread `sub` owns channels [4*sub, 4*sub+3]
// ---------------------------------------------------------------------------
__global__ void edge_kernel(const float* __restrict__ emb,
                            const float* __restrict__ sh0,
                            const float* __restrict__ sh1,
                            const int*   __restrict__ src,
                            const int*   __restrict__ dst,
                            const float* __restrict__ Wm1,
                            const float* __restrict__ Wm2) {
    __shared__ float sWm1[64];
    __shared__ float sWm2[1280];
    for (int i = threadIdx.x; i < 64; i += blockDim.x) sWm1[i] = Wm1[i];
    for (int i = threadIdx.x; i < 1280; i += blockDim.x) sWm2[i] = Wm2[i];
    __syncthreads();

    const int t = blockIdx.x * blockDim.x + threadIdx.x;
    const int e = t >> 3;
    if (e >= N_EDGES) return;
    const int sub = t & 7;
    const int u0 = sub * 4;

    // ---- radial MLP: h = silu(emb @ Wm1 / sqrt8); w = h @ Wm2 / sqrt8 ----
    float embv = emb[e * 8 + sub];
    float hacc = 0.f;
#pragma unroll
    for (int k = 0; k < 8; k++) {
        float ek = __shfl_sync(0xffffffffu, embv, k, 8);
        hacc += ek * sWm1[k * 8 + sub];
    }
    hacc *= INV_SQRT8;
    float h = hacc / (1.f + expf(-hacc));   // silu

    float w[5][4];
#pragma unroll
    for (int p = 0; p < 5; p++)
#pragma unroll
        for (int j = 0; j < 4; j++) w[p][j] = 0.f;

#pragma unroll
    for (int k = 0; k < 8; k++) {
        float hk = __shfl_sync(0xffffffffu, h, k, 8);
        const float* wrow = &sWm2[k * 160 + u0];
#pragma unroll
        for (int p = 0; p < 5; p++)
#pragma unroll
            for (int j = 0; j < 4; j++)
                w[p][j] += hk * wrow[p * 32 + j];
    }
    const float wscale = INV_SQRT8 * NEIGH_INV;
#pragma unroll
    for (int p = 0; p < 5; p++)
#pragma unroll
        for (int j = 0; j < 4; j++) w[p][j] *= wscale;

    // ---- gather source features (L2-resident scratch) ----
    const int ns = __ldg(&src[e]);
    const int nd = __ldg(&dst[e]);
    const float q0  = __ldg(&sh0[e]);
    const float s1x = __ldg(&sh1[e * 3 + 0]);
    const float s1y = __ldg(&sh1[e * 3 + 1]);
    const float s1z = __ldg(&sh1[e * 3 + 2]);

    const float4 S  = *reinterpret_cast<const float4*>(g_xs + ns * 32 + u0);
    const float4 VX = *reinterpret_cast<const float4*>(g_xv + ns * 96 + u0);
    const float4 VY = *reinterpret_cast<const float4*>(g_xv + ns * 96 + 32 + u0);
    const float4 VZ = *reinterpret_cast<const float4*>(g_xv + ns * 96 + 64 + u0);
    const float s_[4] = {S.x, S.y, S.z, S.w};
    const float vx[4] = {VX.x, VX.y, VX.z, VX.w};
    const float vy[4] = {VY.x, VY.y, VY.z, VY.w};
    const float vz[4] = {VZ.x, VZ.y, VZ.z, VZ.w};

    float P1[4], P2[4], P3[3][4], P4[3][4], P5[3][4];
#pragma unroll
    for (int j = 0; j < 4; j++) {
        const float dot = vx[j] * s1x + vy[j] * s1y + vz[j] * s1z;
        const float cx = vy[j] * s1z - vz[j] * s1y;
        const float cy = vz[j] * s1x - vx[j] * s1z;
        const float cz = vx[j] * s1y - vy[j] * s1x;
        P1[j]    = w[0][j] * s_[j] * q0;
        P2[j]    = w[1][j] * dot * CG_INV3;
        P3[0][j] = w[2][j] * s_[j] * s1x;
        P3[1][j] = w[2][j] * s_[j] * s1y;
        P3[2][j] = w[2][j] * s_[j] * s1z;
        P4[0][j] = w[3][j] * vx[j] * q0;
        P4[1][j] = w[3][j] * vy[j] * q0;
        P4[2][j] = w[3][j] * vz[j] * q0;
        P5[0][j] = w[4][j] * cx * CG_INV2;
        P5[1][j] = w[4][j] * cy * CG_INV2;
        P5[2][j] = w[4][j] * cz * CG_INV2;
    }

    float* as_base = g_aggs + nd * 64 + u0;
    red_add_v4(as_base,      P1[0], P1[1], P1[2], P1[3]);
    red_add_v4(as_base + 32, P2[0], P2[1], P2[2], P2[3]);
#pragma unroll
    for (int c = 0; c < 3; c++) {
        float* av_base = g_aggv + nd * 288 + c * 96 + u0;
        red_add_v4(av_base,      P3[c][0], P3[c][1], P3[c][2], P3[c][3]);
        red_add_v4(av_base + 32, P4[c][0], P4[c][1], P4[c][2], P4[c][3]);
        red_add_v4(av_base + 64, P5[c][0], P5[c][1], P5[c][2], P5[c][3]);
    }
}

// ---------------------------------------------------------------------------
// Kernel 3: linear_2 + self-connection TP + output.
// ONE THREAD PER NODE. All 32 output channels in registers; weights
// (prescaled) live in dynamic smem and are read via uniform broadcast
// LDS.128 (all lanes same address -> conflict-free, 1 wavefront).
// No shuffles anywhere.
// ---------------------------------------------------------------------------
#define SM_W2S   0        // 2048 floats
#define SM_W2V   2048     // 3072 floats
#define SM_WSCS  5120     // 8192 floats
#define SM_WSCV  13312    // 8192 floats
#define SM_TOTAL 21504    // floats (86016 bytes)

__global__ __launch_bounds__(256) void node_out_kernel(
        const float* __restrict__ node_s,
        const float* __restrict__ node_v,
        const float* __restrict__ attrs,
        const float* __restrict__ W2s,
        const float* __restrict__ W2v,
        const float* __restrict__ Wscs,
        const float* __restrict__ Wscv,
        float* __restrict__ out) {
    extern __shared__ float sw[];
    // stage + prescale weights (fold the normalization constants)
    for (int i = threadIdx.x; i < 2048; i += blockDim.x)
        sw[SM_W2S + i] = W2s[i] * MS_SCALE;
    for (int i = threadIdx.x; i < 3072; i += blockDim.x)
        sw[SM_W2V + i] = W2v[i] * MV_SCALE;
    for (int i = threadIdx.x; i < 8192; i += blockDim.x) {
        sw[SM_WSCS + i] = Wscs[i] * NSC_SCALE;
        sw[SM_WSCV + i] = Wscv[i] * NSC_SCALE;
    }
    __syncthreads();

    const int n = blockIdx.x * blockDim.x + threadIdx.x;
    if (n >= N_NODES) return;

    // node attrs (8 floats)
    float at[8];
    {
        const float4 a0 = *reinterpret_cast<const float4*>(attrs + n * 8);
        const float4 a1 = *reinterpret_cast<const float4*>(attrs + n * 8 + 4);
        at[0]=a0.x; at[1]=a0.y; at[2]=a0.z; at[3]=a0.w;
        at[4]=a1.x; at[5]=a1.y; at[6]=a1.z; at[7]=a1.w;
    }

    // ====================== Phase 1: out_s = m_s + sc_s ======================
    {
        float acc[32];
#pragma unroll
        for (int v = 0; v < 32; v++) acc[v] = 0.f;

        // m_s: agg_s[64] @ W2s[64,32]
        const float4* in4 = reinterpret_cast<const float4*>(g_aggs + n * 64);
        for (int k4 = 0; k4 < 16; k4++) {
            const float4 iv = in4[k4];
            const float in[4] = {iv.x, iv.y, iv.z, iv.w};
#pragma unroll
            for (int j = 0; j < 4; j++) {
                const float ik = in[j];
                const float4* wr = reinterpret_cast<const float4*>(sw + SM_W2S + (k4 * 4 + j) * 32);
#pragma unroll
                for (int v4 = 0; v4 < 8; v4++) {
                    const float4 wv = wr[v4];
                    acc[v4*4+0] += ik * wv.x;
                    acc[v4*4+1] += ik * wv.y;
                    acc[v4*4+2] += ik * wv.z;
                    acc[v4*4+3] += ik * wv.w;
                }
            }
        }

        // sc_s: sum_{u,a} node_s[u]*attr[a]*Wscs[u,a,v]
        const float4* ns4 = reinterpret_cast<const float4*>(node_s + n * 32);
        for (int u4 = 0; u4 < 8; u4++) {
            const float4 sv = ns4[u4];
            const float su[4] = {sv.x, sv.y, sv.z, sv.w};
#pragma unroll
            for (int j = 0; j < 4; j++) {
                const int u = u4 * 4 + j;
#pragma unroll
                for (int a = 0; a < 8; a++) {
                    const float za = su[j] * at[a];
                    const float4* wr = reinterpret_cast<const float4*>(sw + SM_WSCS + (u * 8 + a) * 32);
#pragma unroll
                    for (int v4 = 0; v4 < 8; v4++) {
                        const float4 wv = wr[v4];
                        acc[v4*4+0] += za * wv.x;
                        acc[v4*4+1] += za * wv.y;
                        acc[v4*4+2] += za * wv.z;
                        acc[v4*4+3] += za * wv.w;
                    }
                }
            }
        }

        // store out_s
        float4* o4 = reinterpret_cast<float4*>(out + n * 128);
#pragma unroll
        for (int v4 = 0; v4 < 8; v4++)
            o4[v4] = make_float4(acc[v4*4+0], acc[v4*4+1], acc[v4*4+2], acc[v4*4+3]);
    }

    // ====================== Phase 2: out_v = m_v + sc_v ======================
    {
        float accv[3][32];
#pragma unroll
        for (int c = 0; c < 3; c++)
#pragma unroll
            for (int v = 0; v < 32; v++) accv[c][v] = 0.f;

        // m_v: per component, agg_v[c][96] @ W2v[96,32]
#pragma unroll 1
        for (int c = 0; c < 3; c++) {
            const float4* in4 = reinterpret_cast<const float4*>(g_aggv + n * 288 + c * 96);
            for (int k4 = 0; k4 < 24; k4++) {
                const float4 iv = in4[k4];
                const float in[4] = {iv.x, iv.y, iv.z, iv.w};
#pragma unroll
                for (int j = 0; j < 4; j++) {
                    const float ik = in[j];
                    const float4* wr = reinterpret_cast<const float4*>(sw + SM_W2V + (k4 * 4 + j) * 32);
#pragma unroll
                    for (int v4 = 0; v4 < 8; v4++) {
                        const float4 wv = wr[v4];
                        accv[c][v4*4+0] += ik * wv.x;
                        accv[c][v4*4+1] += ik * wv.y;
                        accv[c][v4*4+2] += ik * wv.z;
                        accv[c][v4*4+3] += ik * wv.w;
                    }
                }
            }
        }

        // sc_v: M[u,v] = sum_a attr[a]*Wscv[u,a,v], formed once per u and
        // reused for all 3 vector components.
        const float* nv = node_v + n * 96;
        for (int u = 0; u < 32; u++) {
            float mv[32];
#pragma unroll
            for (int v = 0; v < 32; v++) mv[v] = 0.f;
#pragma unroll
            for (int a = 0; a < 8; a++) {
                const float wa = at[a];
                const float4* wr = reinterpret_cast<const float4*>(sw + SM_WSCV + (u * 8 + a) * 32);
#pragma unroll
                for (int v4 = 0; v4 < 8; v4++) {
                    const float4 wv = wr[v4];
                    mv[v4*4+0] += wa * wv.x;
                    mv[v4*4+1] += wa * wv.y;
                    mv[v4*4+2] += wa * wv.z;
                    mv[v4*4+3] += wa * wv.w;
                }
            }
            const float vu0 = nv[u * 3 + 0];
            const float vu1 = nv[u * 3 + 1];
            const float vu2 = nv[u * 3 + 2];
#pragma unroll
            for (int v = 0; v < 32; v++) {
                accv[0][v] += vu0 * mv[v];
                accv[1][v] += vu1 * mv[v];
                accv[2][v] += vu2 * mv[v];
            }
        }

        // store out_v: out[n*128 + 32 + v*3 + c], packed into float4 groups
        float4* o4 = reinterpret_cast<float4*>(out + n * 128 + 32);
#pragma unroll
        for (int g = 0; g < 24; g++) {
            float4 o;
            o.x = accv[(g*4+0)%3][(g*4+0)/3];
            o.y = accv[(g*4+1)%3][(g*4+1)/3];
            o.z = accv[(g*4+2)%3][(g*4+2)/3];
            o.w = accv[(g*4+3)%3][(g*4+3)/3];
            o4[g] = o;
        }
    }
}

// ---------------------------------------------------------------------------
extern "C" void kernel_launch(void* const* d_in, const int* in_sizes, int n_in,
                              void* d_out, int out_size) {
    const float* node_s     = (const float*)d_in[0];
    const float* node_v     = (const float*)d_in[1];
    const float* node_attrs = (const float*)d_in[2];
    const float* edge_emb   = (const float*)d_in[3];
    const float* edge_sh0   = (const float*)d_in[4];
    const float* edge_sh1   = (const float*)d_in[5];
    const float* W1_s       = (const float*)d_in[6];
    const float* W1_v       = (const float*)d_in[7];
    const float* Wm1        = (const float*)d_in[8];
    const float* Wm2        = (const float*)d_in[9];
    const float* W2_s       = (const float*)d_in[10];
    const float* W2_v       = (const float*)d_in[11];
    const float* Wsc_s      = (const float*)d_in[12];
    const float* Wsc_v      = (const float*)d_in[13];
    const int*   edge_src   = (const int*)d_in[14];
    const int*   edge_dst   = (const int*)d_in[15];
    float* out = (float*)d_out;

    cudaFuncSetAttribute(node_out_kernel,
                         cudaFuncAttributeMaxDynamicSharedMemorySize, SM_TOTAL * sizeof(float));

    zero_kernel<<<2048, 256>>>();
    lin1_kernel<<<(N_NODES + 7) / 8, 256>>>(node_s, node_v, W1_s, W1_v);
    edge_kernel<<<(N_EDGES * 8 + 255) / 256, 256>>>(edge_emb, edge_sh0, edge_sh1,
                                                    edge_src, edge_dst, Wm1, Wm2);
    node_out_kernel<<<(N_NODES + 255) / 256, 256, SM_TOTAL * sizeof(float)>>>(
        node_s, node_v, node_attrs, W2_s, W2_v, Wsc_s, Wsc_v, out);
}

// round 7
// speedup vs baseline: 1.1360x; 1.1360x over previous
#include <cuda_runtime.h>
#include <math.h>

#define N_NODES 50000
#define N_EDGES 800000

#define INV_SQRT8  0.35355339059327373f
#define INV_SQRT32 0.17677669529663687f
#define CG_INV3    0.5773502691896258f   // 1/sqrt(3)
#define CG_INV2    0.7071067811865476f   // 1/sqrt(2)
#define MS_SCALE   0.125f                // 1/sqrt(64)
#define MV_SCALE   0.10206207261596575f  // 1/sqrt(96)
#define NSC_SCALE  0.0625f               // 1/sqrt(256)
#define NEIGH_INV  0.25f                 // 1/sqrt(16)

// Scratch (static device memory — no allocation in kernel_launch)
__device__ __align__(16) float g_xs[N_NODES * 32];    // linear_1 scalar out
__device__ __align__(16) float g_xv[N_NODES * 96];    // linear_1 vector out, [N][3][32] comp-major
__device__ __align__(16) float g_aggs[N_NODES * 64];  // scatter target, [N][64]
__device__ __align__(16) float g_aggv[N_NODES * 288]; // scatter target, [N][3][96] comp-major

__device__ __forceinline__ void red_add_v4(float* addr, float a, float b, float c, float d) {
    asm volatile("red.global.add.v4.f32 [%0], {%1, %2, %3, %4};"
                 :: "l"(addr), "f"(a), "f"(b), "f"(c), "f"(d) : "memory");
}

// ---------------------------------------------------------------------------
// Kernel 0: zero the aggregation buffers
// ---------------------------------------------------------------------------
__global__ void zero_kernel() {
    const int stride = gridDim.x * blockDim.x;
    int i = blockIdx.x * blockDim.x + threadIdx.x;
    const float4 z = make_float4(0.f, 0.f, 0.f, 0.f);
    const int tot_s = N_NODES * 64 / 4;
    const int tot_v = N_NODES * 288 / 4;
    for (int k = i; k < tot_s; k += stride) reinterpret_cast<float4*>(g_aggs)[k] = z;
    for (int k = i; k < tot_v; k += stride) reinterpret_cast<float4*>(g_aggv)[k] = z;
}

// ---------------------------------------------------------------------------
// Kernel 1: linear_1 (per-l channel mixing), one warp per node
// ---------------------------------------------------------------------------
__global__ void lin1_kernel(const float* __restrict__ node_s,
                            const float* __restrict__ node_v,
                            const float* __restrict__ W1s,
                            const float* __restrict__ W1v) {
    __shared__ float sW1s[1024];
    __shared__ float sW1v[1024];
    for (int i = threadIdx.x; i < 1024; i += blockDim.x) {
        sW1s[i] = W1s[i];
        sW1v[i] = W1v[i];
    }
    __syncthreads();

    const int warp = (blockIdx.x * blockDim.x + threadIdx.x) >> 5;
    const int lane = threadIdx.x & 31;
    if (warp >= N_NODES) return;
    const int n = warp;

    float sl = node_s[n * 32 + lane];
    float acc = 0.f;
#pragma unroll
    for (int u = 0; u < 32; u++)
        acc += __shfl_sync(0xffffffffu, sl, u) * sW1s[u * 32 + lane];
    g_xs[n * 32 + lane] = acc * INV_SQRT32;

#pragma unroll
    for (int c = 0; c < 3; c++) {
        float vl = node_v[n * 96 + lane * 3 + c];
        float a = 0.f;
#pragma unroll
        for (int u = 0; u < 32; u++)
            a += __shfl_sync(0xffffffffu, vl, u) * sW1v[u * 32 + lane];
        g_xv[n * 96 + c * 32 + lane] = a * INV_SQRT32;
    }
}

// ---------------------------------------------------------------------------
// Kernel 2: per-edge radial MLP + CG tensor product + scatter via red.v4
// 8 threads per edge; thread `sub` owns channels [4*sub, 4*sub+3]
// ---------------------------------------------------------------------------
__global__ void edge_kernel(const float* __restrict__ emb,
                            const float* __restrict__ sh0,
                            const float* __restrict__ sh1,
                            const int*   __restrict__ src,
                            const int*   __restrict__ dst,
                            const float* __restrict__ Wm1,
                            const float* __restrict__ Wm2) {
    __shared__ float sWm1[64];
    __shared__ float sWm2[1280];
    for (int i = threadIdx.x; i < 64; i += blockDim.x) sWm1[i] = Wm1[i];
    for (int i = threadIdx.x; i < 1280; i += blockDim.x) sWm2[i] = Wm2[i];
    __syncthreads();

    const int t = blockIdx.x * blockDim.x + threadIdx.x;
    const int e = t >> 3;
    if (e >= N_EDGES) return;
    const int sub = t & 7;
    const int u0 = sub * 4;

    // ---- radial MLP ----
    float embv = emb[e * 8 + sub];
    float hacc = 0.f;
#pragma unroll
    for (int k = 0; k < 8; k++) {
        float ek = __shfl_sync(0xffffffffu, embv, k, 8);
        hacc += ek * sWm1[k * 8 + sub];
    }
    hacc *= INV_SQRT8;
    float h = hacc / (1.f + expf(-hacc));   // silu

    float w[5][4];
#pragma unroll
    for (int p = 0; p < 5; p++)
#pragma unroll
        for (int j = 0; j < 4; j++) w[p][j] = 0.f;

#pragma unroll
    for (int k = 0; k < 8; k++) {
        float hk = __shfl_sync(0xffffffffu, h, k, 8);
        const float* wrow = &sWm2[k * 160 + u0];
#pragma unroll
        for (int p = 0; p < 5; p++)
#pragma unroll
            for (int j = 0; j < 4; j++)
                w[p][j] += hk * wrow[p * 32 + j];
    }
    const float wscale = INV_SQRT8 * NEIGH_INV;
#pragma unroll
    for (int p = 0; p < 5; p++)
#pragma unroll
        for (int j = 0; j < 4; j++) w[p][j] *= wscale;

    // ---- gather source features (L2-resident scratch) ----
    const int ns = __ldg(&src[e]);
    const int nd = __ldg(&dst[e]);
    const float q0  = __ldg(&sh0[e]);
    const float s1x = __ldg(&sh1[e * 3 + 0]);
    const float s1y = __ldg(&sh1[e * 3 + 1]);
    const float s1z = __ldg(&sh1[e * 3 + 2]);

    const float4 S  = *reinterpret_cast<const float4*>(g_xs + ns * 32 + u0);
    const float4 VX = *reinterpret_cast<const float4*>(g_xv + ns * 96 + u0);
    const float4 VY = *reinterpret_cast<const float4*>(g_xv + ns * 96 + 32 + u0);
    const float4 VZ = *reinterpret_cast<const float4*>(g_xv + ns * 96 + 64 + u0);
    const float s_[4] = {S.x, S.y, S.z, S.w};
    const float vx[4] = {VX.x, VX.y, VX.z, VX.w};
    const float vy[4] = {VY.x, VY.y, VY.z, VY.w};
    const float vz[4] = {VZ.x, VZ.y, VZ.z, VZ.w};

    float P1[4], P2[4], P3[3][4], P4[3][4], P5[3][4];
#pragma unroll
    for (int j = 0; j < 4; j++) {
        const float dot = vx[j] * s1x + vy[j] * s1y + vz[j] * s1z;
        const float cx = vy[j] * s1z - vz[j] * s1y;
        const float cy = vz[j] * s1x - vx[j] * s1z;
        const float cz = vx[j] * s1y - vy[j] * s1x;
        P1[j]    = w[0][j] * s_[j] * q0;
        P2[j]    = w[1][j] * dot * CG_INV3;
        P3[0][j] = w[2][j] * s_[j] * s1x;
        P3[1][j] = w[2][j] * s_[j] * s1y;
        P3[2][j] = w[2][j] * s_[j] * s1z;
        P4[0][j] = w[3][j] * vx[j] * q0;
        P4[1][j] = w[3][j] * vy[j] * q0;
        P4[2][j] = w[3][j] * vz[j] * q0;
        P5[0][j] = w[4][j] * cx * CG_INV2;
        P5[1][j] = w[4][j] * cy * CG_INV2;
        P5[2][j] = w[4][j] * cz * CG_INV2;
    }

    float* as_base = g_aggs + nd * 64 + u0;
    red_add_v4(as_base,      P1[0], P1[1], P1[2], P1[3]);
    red_add_v4(as_base + 32, P2[0], P2[1], P2[2], P2[3]);
#pragma unroll
    for (int c = 0; c < 3; c++) {
        float* av_base = g_aggv + nd * 288 + c * 96 + u0;
        red_add_v4(av_base,      P3[c][0], P3[c][1], P3[c][2], P3[c][3]);
        red_add_v4(av_base + 32, P4[c][0], P4[c][1], P4[c][2], P4[c][3]);
        red_add_v4(av_base + 64, P5[c][0], P5[c][1], P5[c][2], P5[c][3]);
    }
}

// ---------------------------------------------------------------------------
// Kernel 3a: scalar output = agg_s @ W2s + self-connection (scalar path).
// 4 THREADS PER NODE, each owns 8 output channels. Weights prescaled in smem,
// read as LDS.128 (quads hit 4 consecutive 16B segments -> conflict-free).
// ---------------------------------------------------------------------------
__global__ __launch_bounds__(256) void node_s_kernel(
        const float* __restrict__ node_s,
        const float* __restrict__ attrs,
        const float* __restrict__ W2s,
        const float* __restrict__ Wscs,
        float* __restrict__ out) {
    extern __shared__ float sw[];
    float* sW2s  = sw;          // 2048 floats
    float* sWscs = sw + 2048;   // 8192 floats
    for (int i = threadIdx.x; i < 2048; i += blockDim.x)
        sW2s[i] = W2s[i] * MS_SCALE;
    for (int i = threadIdx.x; i < 8192; i += blockDim.x)
        sWscs[i] = Wscs[i] * NSC_SCALE;
    __syncthreads();

    const int gt = blockIdx.x * blockDim.x + threadIdx.x;
    const int n = gt >> 2;
    if (n >= N_NODES) return;
    const int ch0 = (gt & 3) * 8;

    float acc[8];
#pragma unroll
    for (int j = 0; j < 8; j++) acc[j] = 0.f;

    // m_s: agg_s[64] @ W2s[64,32]
    const float4* in4 = reinterpret_cast<const float4*>(g_aggs + n * 64);
#pragma unroll 4
    for (int k4 = 0; k4 < 16; k4++) {
        const float4 iv = in4[k4];
        const float in[4] = {iv.x, iv.y, iv.z, iv.w};
#pragma unroll
        for (int j = 0; j < 4; j++) {
            const float ik = in[j];
            const float4* wr = reinterpret_cast<const float4*>(sW2s + (k4 * 4 + j) * 32 + ch0);
            const float4 w0 = wr[0];
            const float4 w1 = wr[1];
            acc[0] += ik * w0.x; acc[1] += ik * w0.y;
            acc[2] += ik * w0.z; acc[3] += ik * w0.w;
            acc[4] += ik * w1.x; acc[5] += ik * w1.y;
            acc[6] += ik * w1.z; acc[7] += ik * w1.w;
        }
    }

    // sc_s: sum_{u,a} node_s[u]*attr[a]*Wscs[u,a,v]
    float at[8];
    {
        const float4 a0 = *reinterpret_cast<const float4*>(attrs + n * 8);
        const float4 a1 = *reinterpret_cast<const float4*>(attrs + n * 8 + 4);
        at[0]=a0.x; at[1]=a0.y; at[2]=a0.z; at[3]=a0.w;
        at[4]=a1.x; at[5]=a1.y; at[6]=a1.z; at[7]=a1.w;
    }
    const float4* ns4 = reinterpret_cast<const float4*>(node_s + n * 32);
#pragma unroll 2
    for (int u4 = 0; u4 < 8; u4++) {
        const float4 sv = ns4[u4];
        const float su[4] = {sv.x, sv.y, sv.z, sv.w};
#pragma unroll
        for (int j = 0; j < 4; j++) {
            const int u = u4 * 4 + j;
#pragma unroll
            for (int a = 0; a < 8; a++) {
                const float za = su[j] * at[a];
                const float4* wr = reinterpret_cast<const float4*>(sWscs + (u * 8 + a) * 32 + ch0);
                const float4 w0 = wr[0];
                const float4 w1 = wr[1];
                acc[0] += za * w0.x; acc[1] += za * w0.y;
                acc[2] += za * w0.z; acc[3] += za * w0.w;
                acc[4] += za * w1.x; acc[5] += za * w1.y;
                acc[6] += za * w1.z; acc[7] += za * w1.w;
            }
        }
    }

    float4* o4 = reinterpret_cast<float4*>(out + n * 128 + ch0);
    o4[0] = make_float4(acc[0], acc[1], acc[2], acc[3]);
    o4[1] = make_float4(acc[4], acc[5], acc[6], acc[7]);
}

// ---------------------------------------------------------------------------
// Kernel 3b: vector output = agg_v @ W2v + self-connection (vector path).
// 4 THREADS PER NODE, each owns 8 output channels x 3 components.
// ---------------------------------------------------------------------------
__global__ __launch_bounds__(256) void node_v_kernel(
        const float* __restrict__ node_v,
        const float* __restrict__ attrs,
        const float* __restrict__ W2v,
        const float* __restrict__ Wscv,
        float* __restrict__ out) {
    extern __shared__ float sw[];
    float* sW2v  = sw;          // 3072 floats
    float* sWscv = sw + 3072;   // 8192 floats
    for (int i = threadIdx.x; i < 3072; i += blockDim.x)
        sW2v[i] = W2v[i] * MV_SCALE;
    for (int i = threadIdx.x; i < 8192; i += blockDim.x)
        sWscv[i] = Wscv[i] * NSC_SCALE;
    __syncthreads();

    const int gt = blockIdx.x * blockDim.x + threadIdx.x;
    const int n = gt >> 2;
    if (n >= N_NODES) return;
    const int ch0 = (gt & 3) * 8;

    float accv[3][8];
#pragma unroll
    for (int c = 0; c < 3; c++)
#pragma unroll
        for (int j = 0; j < 8; j++) accv[c][j] = 0.f;

    // m_v: per component c, agg_v[c][96] @ W2v[96,32]
#pragma unroll 1
    for (int c = 0; c < 3; c++) {
        const float4* in4 = reinterpret_cast<const float4*>(g_aggv + n * 288 + c * 96);
#pragma unroll 4
        for (int k4 = 0; k4 < 24; k4++) {
            const float4 iv = in4[k4];
            const float in[4] = {iv.x, iv.y, iv.z, iv.w};
#pragma unroll
            for (int j = 0; j < 4; j++) {
                const float ik = in[j];
                const float4* wr = reinterpret_cast<const float4*>(sW2v + (k4 * 4 + j) * 32 + ch0);
                const float4 w0 = wr[0];
                const float4 w1 = wr[1];
                accv[c][0] += ik * w0.x; accv[c][1] += ik * w0.y;
                accv[c][2] += ik * w0.z; accv[c][3] += ik * w0.w;
                accv[c][4] += ik * w1.x; accv[c][5] += ik * w1.y;
                accv[c][6] += ik * w1.z; accv[c][7] += ik * w1.w;
            }
        }
    }

    // sc_v: M[u, v-slice] = sum_a attr[a]*Wscv[u,a,v], then apply to 3 comps
    float at[8];
    {
        const float4 a0 = *reinterpret_cast<const float4*>(attrs + n * 8);
        const float4 a1 = *reinterpret_cast<const float4*>(attrs + n * 8 + 4);
        at[0]=a0.x; at[1]=a0.y; at[2]=a0.z; at[3]=a0.w;
        at[4]=a1.x; at[5]=a1.y; at[6]=a1.z; at[7]=a1.w;
    }
    const float* nv = node_v + n * 96;
#pragma unroll 2
    for (int u = 0; u < 32; u++) {
        float mv[8];
#pragma unroll
        for (int j = 0; j < 8; j++) mv[j] = 0.f;
#pragma unroll
        for (int a = 0; a < 8; a++) {
            const float wa = at[a];
            const float4* wr = reinterpret_cast<const float4*>(sWscv + (u * 8 + a) * 32 + ch0);
            const float4 w0 = wr[0];
            const float4 w1 = wr[1];
            mv[0] += wa * w0.x; mv[1] += wa * w0.y;
            mv[2] += wa * w0.z; mv[3] += wa * w0.w;
            mv[4] += wa * w1.x; mv[5] += wa * w1.y;
            mv[6] += wa * w1.z; mv[7] += wa * w1.w;
        }
        const float vu0 = nv[u * 3 + 0];
        const float vu1 = nv[u * 3 + 1];
        const float vu2 = nv[u * 3 + 2];
#pragma unroll
        for (int j = 0; j < 8; j++) {
            accv[0][j] += vu0 * mv[j];
            accv[1][j] += vu1 * mv[j];
            accv[2][j] += vu2 * mv[j];
        }
    }

    // store: out[n*128 + 32 + v*3 + c] for v in [ch0, ch0+8) -> 24 contiguous
    // floats at offset 32 + ch0*3 (16B aligned), 6 float4 stores.
    float4* o4 = reinterpret_cast<float4*>(out + n * 128 + 32 + ch0 * 3);
#pragma unroll
    for (int g = 0; g < 6; g++) {
        float4 o;
        const int f0 = g * 4;
        o.x = accv[(f0 + 0) % 3][(f0 + 0) / 3];
        o.y = accv[(f0 + 1) % 3][(f0 + 1) / 3];
        o.z = accv[(f0 + 2) % 3][(f0 + 2) / 3];
        o.w = accv[(f0 + 3) % 3][(f0 + 3) / 3];
        o4[g] = o;
    }
}

// ---------------------------------------------------------------------------
extern "C" void kernel_launch(void* const* d_in, const int* in_sizes, int n_in,
                              void* d_out, int out_size) {
    const float* node_s     = (const float*)d_in[0];
    const float* node_v     = (const float*)d_in[1];
    const float* node_attrs = (const float*)d_in[2];
    const float* edge_emb   = (const float*)d_in[3];
    const float* edge_sh0   = (const float*)d_in[4];
    const float* edge_sh1   = (const float*)d_in[5];
    const float* W1_s       = (const float*)d_in[6];
    const float* W1_v       = (const float*)d_in[7];
    const float* Wm1        = (const float*)d_in[8];
    const float* Wm2        = (const float*)d_in[9];
    const float* W2_s       = (const float*)d_in[10];
    const float* W2_v       = (const float*)d_in[11];
    const float* Wsc_s      = (const float*)d_in[12];
    const float* Wsc_v      = (const float*)d_in[13];
    const int*   edge_src   = (const int*)d_in[14];
    const int*   edge_dst   = (const int*)d_in[15];
    float* out = (float*)d_out;

    cudaFuncSetAttribute(node_s_kernel,
                         cudaFuncAttributeMaxDynamicSharedMemorySize, 10240 * sizeof(float));
    cudaFuncSetAttribute(node_v_kernel,
                         cudaFuncAttributeMaxDynamicSharedMemorySize, 11264 * sizeof(float));

    zero_kernel<<<2048, 256>>>();
    lin1_kernel<<<(N_NODES + 7) / 8, 256>>>(node_s, node_v, W1_s, W1_v);
    edge_kernel<<<(N_EDGES * 8 + 255) / 256, 256>>>(edge_emb, edge_sh0, edge_sh1,
                                                    edge_src, edge_dst, Wm1, Wm2);
    node_s_kernel<<<(N_NODES * 4 + 255) / 256, 256, 10240 * sizeof(float)>>>(
        node_s, node_attrs, W2_s, Wsc_s, out);
    node_v_kernel<<<(N_NODES * 4 + 255) / 256, 256, 11264 * sizeof(float)>>>(
        node_v, node_attrs, W2_v, Wsc_v, out);
}